// round 8
// baseline (speedup 1.0000x reference)
#include <cuda_runtime.h>

// NSLayer: out = (Q)X where Q = w0 A + ... + w6 A^7 + (w7+1) I,  A = I - X X^T
// 262144 independent 8x8 fp32 matrices, one thread per matrix.
// KEY INSIGHT (R6): FFMA2 is RF-bank limited to rt=3 (3 even + 3 odd distinct
// regs), so the only win is fewer fma-pipe cycles. All powers of A and all
// Horner partial products are SYMMETRIC (polynomials in A commute with A), so
// each product computes only the 36-entry lower triangle via packed dots +
// horizontal adds, then mirrors by repacking. 1.46x fma-cycle reduction.

static constexpr int MPB = 128;   // matrices per block == threads per block
static constexpr int MS  = 68;    // padded matrix stride in floats

typedef unsigned long long u64;

__device__ __forceinline__ u64 pack2(float lo, float hi) {
    u64 r; asm("mov.b64 %0, {%1, %2};" : "=l"(r) : "f"(lo), "f"(hi)); return r;
}
__device__ __forceinline__ float hadd2(u64 v) {
    float lo, hi; asm("mov.b64 {%0, %1}, %2;" : "=f"(lo), "=f"(hi) : "l"(v));
    return lo + hi;
}
__device__ __forceinline__ u64 fma2(u64 a, u64 b, u64 c) {
    u64 d; asm("fma.rn.f32x2 %0, %1, %2, %3;" : "=l"(d) : "l"(a), "l"(b), "l"(c)); return d;
}
__device__ __forceinline__ u64 mul2(u64 a, u64 b) {
    u64 d; asm("mul.rn.f32x2 %0, %1, %2;" : "=l"(d) : "l"(a), "l"(b)); return d;
}
__device__ __forceinline__ u64 add2(u64 a, u64 b) {
    u64 d; asm("add.rn.f32x2 %0, %1, %2;" : "=l"(d) : "l"(a), "l"(b)); return d;
}

#define TRI(r, k) ((r) >= (k) ? ((r) * ((r) + 1) / 2 + (k)) : ((k) * ((k) + 1) / 2 + (r)))

__global__ __launch_bounds__(128, 3)
void nslayer_kernel(const float* __restrict__ x,
                    const float* __restrict__ weight,
                    float* __restrict__ out)
{
    __shared__ float s[MPB * MS];
    const int tid = threadIdx.x;
    const size_t base = (size_t)blockIdx.x * (MPB * 64);

    // ---- preload weights ----
    const float4 wA4 = __ldg(reinterpret_cast<const float4*>(weight));
    const float4 wB4 = __ldg(reinterpret_cast<const float4*>(weight) + 1);
    const float wv[8] = { wA4.x, wA4.y, wA4.z, wA4.w, wB4.x, wB4.y, wB4.z, wB4.w };

    // ---- coalesced load: block's 32KB chunk -> padded smem ----
    const float4* gin = reinterpret_cast<const float4*>(x + base);
#pragma unroll
    for (int k = 0; k < 16; k++) {
        int l4 = tid + k * 128;
        float4 v = gin[l4];
        int l = l4 << 2, m = l >> 6, w = l & 63;
        *reinterpret_cast<float4*>(&s[m * MS + w]) = v;
    }
    __syncthreads();

    // ---- A = I - X X^T : triangle via packed dots, mirror into full A2 ----
    u64 A2[8][4];   // row-major pairs: A2[r][cp] = {A[r][2cp], A[r][2cp+1]}
    {
        u64 X2[8][4];
#pragma unroll
        for (int r = 0; r < 8; r++) {
            ulonglong2 p0 = *reinterpret_cast<const ulonglong2*>(&s[tid * MS + r * 8]);
            ulonglong2 p1 = *reinterpret_cast<const ulonglong2*>(&s[tid * MS + r * 8 + 4]);
            X2[r][0] = p0.x; X2[r][1] = p0.y; X2[r][2] = p1.x; X2[r][3] = p1.y;
        }
        float Cs[36];
#pragma unroll
        for (int r = 0; r < 8; r++)
#pragma unroll
            for (int c = 0; c <= r; c++) {
                u64 d2 = mul2(X2[r][0], X2[c][0]);
#pragma unroll
                for (int kp = 1; kp < 4; kp++) d2 = fma2(X2[r][kp], X2[c][kp], d2);
                Cs[TRI(r, c)] = ((r == c) ? 1.0f : 0.0f) - hadd2(d2);
            }
#pragma unroll
        for (int r = 0; r < 8; r++)
#pragma unroll
            for (int cp = 0; cp < 4; cp++)
                A2[r][cp] = pack2(Cs[TRI(r, 2 * cp)], Cs[TRI(r, 2 * cp + 1)]);
    }   // X2 registers die here

    // ---- M = w6*A + w5*I ----
    u64 M2[8][4];
    {
        const u64 w6_2 = pack2(wv[6], wv[6]);
#pragma unroll
        for (int r = 0; r < 8; r++)
#pragma unroll
            for (int cp = 0; cp < 4; cp++) M2[r][cp] = mul2(w6_2, A2[r][cp]);
        const u64 d_lo = pack2(wv[5], 0.0f), d_hi = pack2(0.0f, wv[5]);
#pragma unroll
        for (int r = 0; r < 8; r++)
            M2[r][r >> 1] = add2(M2[r][r >> 1], (r & 1) ? d_hi : d_lo);
    }

    // ---- 5 symmetric Horner steps: M <- M*A + w[i]*I  (i = 4..0) ----
#pragma unroll
    for (int i = 4; i >= 0; i--) {
        float Cs[36];
#pragma unroll
        for (int r = 0; r < 8; r++)
#pragma unroll
            for (int c = 0; c <= r; c++) {
                u64 d2 = mul2(M2[r][0], A2[c][0]);
#pragma unroll
                for (int kp = 1; kp < 4; kp++) d2 = fma2(M2[r][kp], A2[c][kp], d2);
                float p = hadd2(d2);
                Cs[TRI(r, c)] = (r == c) ? (p + wv[i]) : p;
            }
#pragma unroll
        for (int r = 0; r < 8; r++)
#pragma unroll
            for (int cp = 0; cp < 4; cp++)
                M2[r][cp] = pack2(Cs[TRI(r, 2 * cp)], Cs[TRI(r, 2 * cp + 1)]);
    }

    // ---- final step: Q = M*A + (w7+1)*I, packed as {v,v} broadcasts ----
    u64 Qb[36];
    {
        const float w7p1 = wv[7] + 1.0f;
#pragma unroll
        for (int r = 0; r < 8; r++)
#pragma unroll
            for (int c = 0; c <= r; c++) {
                u64 d2 = mul2(M2[r][0], A2[c][0]);
#pragma unroll
                for (int kp = 1; kp < 4; kp++) d2 = fma2(M2[r][kp], A2[c][kp], d2);
                float p = hadd2(d2);
                float v = (r == c) ? (p + w7p1) : p;
                Qb[TRI(r, c)] = pack2(v, v);
            }
    }   // M2, A2 die here

    // ---- out = Q * X : reload X from smem (still intact), column pairs ----
    {
        u64 X2[8][4];
#pragma unroll
        for (int r = 0; r < 8; r++) {
            ulonglong2 p0 = *reinterpret_cast<const ulonglong2*>(&s[tid * MS + r * 8]);
            ulonglong2 p1 = *reinterpret_cast<const ulonglong2*>(&s[tid * MS + r * 8 + 4]);
            X2[r][0] = p0.x; X2[r][1] = p0.y; X2[r][2] = p1.x; X2[r][3] = p1.y;
        }
#pragma unroll
        for (int cp = 0; cp < 4; cp++) {
            u64 t2[8];
#pragma unroll
            for (int r = 0; r < 8; r++) {
                u64 d2 = mul2(Qb[TRI(r, 0)], X2[0][cp]);
#pragma unroll
                for (int k = 1; k < 8; k++)
                    d2 = fma2(Qb[TRI(r, k)], X2[k][cp], d2);
                t2[r] = d2;
            }
            // write this column-pair of the result into my smem region
#pragma unroll
            for (int r = 0; r < 8; r++)
                *reinterpret_cast<u64*>(&s[tid * MS + r * 8 + 2 * cp]) = t2[r];
        }
    }
    __syncthreads();

    // ---- coalesced store: padded smem -> block's 32KB output chunk ----
    float4* gout = reinterpret_cast<float4*>(out + base);
#pragma unroll
    for (int k = 0; k < 16; k++) {
        int l4 = tid + k * 128;
        int l = l4 << 2, m = l >> 6, w = l & 63;
        gout[l4] = *reinterpret_cast<const float4*>(&s[m * MS + w]);
    }
}

extern "C" void kernel_launch(void* const* d_in, const int* in_sizes, int n_in,
                              void* d_out, int out_size) {
    const float* x = (const float*)d_in[0];
    const float* w = (const float*)d_in[1];
    float* out = (float*)d_out;
    int nmat = in_sizes[0] / 64;          // 262144
    int blocks = nmat / MPB;              // 2048 (exact)
    nslayer_kernel<<<blocks, MPB>>>(x, w, out);
}

// round 9
// speedup vs baseline: 1.1891x; 1.1891x over previous
#include <cuda_runtime.h>

// NSLayer: out = X + (w0 A + ... + w6 A^7 + w7 I) X,  A = I - X X^T
// 262144 independent 8x8 fp32 matrices, ONE thread per matrix.
// R7 scheme (even/odd power split, B = A^2):
//   V = BX, W = BV, Z = BW
//   t = w0 X + w2 V + w4 W + w6 Z
//   u = (1+w7) X + w1 V + w3 W + w5 Z
//   out = u + A t
// fma2 budget/thread: Gram 144 + B 288 (broadcast x broadcast, result is
// ALREADY broadcast-packed -> zero alu repacking) + 4 col-pairs x 320 = 1712
// vs 2160 for the 7-product chain. FFMA2 rt=3 floor -> ~37us predicted.

static constexpr int MPB = 128;   // matrices per block == threads per block
static constexpr int MS  = 68;    // padded matrix stride in floats

typedef unsigned long long u64;

__device__ __forceinline__ u64 pack2(float lo, float hi) {
    u64 r; asm("mov.b64 %0, {%1, %2};" : "=l"(r) : "f"(lo), "f"(hi)); return r;
}
__device__ __forceinline__ float hadd2(u64 v) {
    float lo, hi; asm("mov.b64 {%0, %1}, %2;" : "=f"(lo), "=f"(hi) : "l"(v));
    return lo + hi;
}
__device__ __forceinline__ u64 fma2(u64 a, u64 b, u64 c) {
    u64 d; asm("fma.rn.f32x2 %0, %1, %2, %3;" : "=l"(d) : "l"(a), "l"(b), "l"(c)); return d;
}
__device__ __forceinline__ u64 mul2(u64 a, u64 b) {
    u64 d; asm("mul.rn.f32x2 %0, %1, %2;" : "=l"(d) : "l"(a), "l"(b)); return d;
}

#define TRI(r, k) ((r) >= (k) ? ((r) * ((r) + 1) / 2 + (k)) : ((k) * ((k) + 1) / 2 + (r)))

__global__ __launch_bounds__(128, 2)
void nslayer_kernel(const float* __restrict__ x,
                    const float* __restrict__ weight,
                    float* __restrict__ out)
{
    __shared__ float s[MPB * MS];
    const int tid = threadIdx.x;
    const size_t base = (size_t)blockIdx.x * (MPB * 64);

    // ---- preload weights, pre-broadcast ----
    const float4 wA4 = __ldg(reinterpret_cast<const float4*>(weight));
    const float4 wB4 = __ldg(reinterpret_cast<const float4*>(weight) + 1);
    const u64 w0_2 = pack2(wA4.x, wA4.x);
    const u64 w1_2 = pack2(wA4.y, wA4.y);
    const u64 w2_2 = pack2(wA4.z, wA4.z);
    const u64 w3_2 = pack2(wA4.w, wA4.w);
    const u64 w4_2 = pack2(wB4.x, wB4.x);
    const u64 w5_2 = pack2(wB4.y, wB4.y);
    const u64 w6_2 = pack2(wB4.z, wB4.z);
    const float w7p1 = wB4.w + 1.0f;
    const u64 w7p1_2 = pack2(w7p1, w7p1);

    // ---- coalesced load: block's 32KB chunk -> padded smem ----
    const float4* gin = reinterpret_cast<const float4*>(x + base);
#pragma unroll
    for (int k = 0; k < 16; k++) {
        int l4 = tid + k * 128;
        float4 v = gin[l4];
        int l = l4 << 2, m = l >> 6, w = l & 63;
        *reinterpret_cast<float4*>(&s[m * MS + w]) = v;
    }
    __syncthreads();

    // ---- A = I - X X^T : triangle via packed row dots -> broadcast form ----
    u64 A2b[36];
    {
        u64 X2[8][4];
#pragma unroll
        for (int r = 0; r < 8; r++) {
            ulonglong2 p0 = *reinterpret_cast<const ulonglong2*>(&s[tid * MS + r * 8]);
            ulonglong2 p1 = *reinterpret_cast<const ulonglong2*>(&s[tid * MS + r * 8 + 4]);
            X2[r][0] = p0.x; X2[r][1] = p0.y; X2[r][2] = p1.x; X2[r][3] = p1.y;
        }
#pragma unroll
        for (int r = 0; r < 8; r++)
#pragma unroll
            for (int c = 0; c <= r; c++) {
                u64 d2 = mul2(X2[r][0], X2[c][0]);
#pragma unroll
                for (int kp = 1; kp < 4; kp++) d2 = fma2(X2[r][kp], X2[c][kp], d2);
                float v = ((r == c) ? 1.0f : 0.0f) - hadd2(d2);
                A2b[TRI(r, c)] = pack2(v, v);
            }
    }   // X2 dies here

    // ---- B = A*A triangle, broadcast x broadcast: result lanes are equal,
    //      so B arrives ALREADY broadcast-packed. Zero alu overhead. ----
    u64 B2b[36];
#pragma unroll
    for (int r = 0; r < 8; r++)
#pragma unroll
        for (int c = 0; c <= r; c++) {
            u64 d2 = mul2(A2b[TRI(r, 0)], A2b[TRI(0, c)]);
#pragma unroll
            for (int k = 1; k < 8; k++)
                d2 = fma2(A2b[TRI(r, k)], A2b[TRI(k, c)], d2);
            B2b[TRI(r, c)] = d2;
        }

    // ---- per column-pair chain: V=BX, W=BV, Z=BW; t,u folds; out=u+A*t ----
#pragma unroll
    for (int cp = 0; cp < 4; cp++) {
        u64 xv[8], t[8], u[8];
#pragma unroll
        for (int k = 0; k < 8; k++)
            xv[k] = *reinterpret_cast<const u64*>(&s[tid * MS + k * 8 + 2 * cp]);

        // v = B x ; t = w0 x + w2 v ; u = (1+w7) x + w1 v
        {
            u64 v[8];
#pragma unroll
            for (int r = 0; r < 8; r++) {
                u64 d2 = mul2(B2b[TRI(r, 0)], xv[0]);
#pragma unroll
                for (int k = 1; k < 8; k++) d2 = fma2(B2b[TRI(r, k)], xv[k], d2);
                v[r] = d2;
            }
#pragma unroll
            for (int r = 0; r < 8; r++) {
                t[r] = fma2(w2_2, v[r], mul2(w0_2, xv[r]));
                u[r] = fma2(w1_2, v[r], mul2(w7p1_2, xv[r]));
            }
            // w = B v ; t += w4 w ; u += w3 w   (xv dead, reuse as w)
#pragma unroll
            for (int r = 0; r < 8; r++) {
                u64 d2 = mul2(B2b[TRI(r, 0)], v[0]);
#pragma unroll
                for (int k = 1; k < 8; k++) d2 = fma2(B2b[TRI(r, k)], v[k], d2);
                xv[r] = d2;
            }
#pragma unroll
            for (int r = 0; r < 8; r++) {
                t[r] = fma2(w4_2, xv[r], t[r]);
                u[r] = fma2(w3_2, xv[r], u[r]);
            }
            // z = B w ; t += w6 z ; u += w5 z   (v dead, reuse as z)
#pragma unroll
            for (int r = 0; r < 8; r++) {
                u64 d2 = mul2(B2b[TRI(r, 0)], xv[0]);
#pragma unroll
                for (int k = 1; k < 8; k++) d2 = fma2(B2b[TRI(r, k)], xv[k], d2);
                v[r] = d2;
            }
#pragma unroll
            for (int r = 0; r < 8; r++) {
                t[r] = fma2(w6_2, v[r], t[r]);
                u[r] = fma2(w5_2, v[r], u[r]);
            }
        }

        // o = u + A t  (accumulate into u), store this column pair
#pragma unroll
        for (int r = 0; r < 8; r++) {
            u64 d2 = u[r];
#pragma unroll
            for (int k = 0; k < 8; k++) d2 = fma2(A2b[TRI(r, k)], t[k], d2);
            *reinterpret_cast<u64*>(&s[tid * MS + r * 8 + 2 * cp]) = d2;
        }
    }
    __syncthreads();

    // ---- coalesced store: padded smem -> block's 32KB output chunk ----
    float4* gout = reinterpret_cast<float4*>(out + base);
#pragma unroll
    for (int k = 0; k < 16; k++) {
        int l4 = tid + k * 128;
        int l = l4 << 2, m = l >> 6, w = l & 63;
        gout[l4] = *reinterpret_cast<const float4*>(&s[m * MS + w]);
    }
}

extern "C" void kernel_launch(void* const* d_in, const int* in_sizes, int n_in,
                              void* d_out, int out_size) {
    const float* x = (const float*)d_in[0];
    const float* w = (const float*)d_in[1];
    float* out = (float*)d_out;
    int nmat = in_sizes[0] / 64;          // 262144
    int blocks = nmat / MPB;              // 2048 (exact)
    nslayer_kernel<<<blocks, MPB>>>(x, w, out);
}